// round 4
// baseline (speedup 1.0000x reference)
#include <cuda_runtime.h>

#define BB 4096
#define TT 365
#define HH 64
#define G4 256
#define HORIZON 7
#define ROWS 32
#define NCTA (BB / ROWS)      // 128
#define NTHREADS 256
#define PW 256

// ---- shared memory layout (float offsets) ----
#define OFF_W0   0
#define OFF_W1   (OFF_W0 + 64 * PW)         // 16384
#define OFF_H0A  (OFF_W1 + 128 * PW)        // 49152  (ping)
#define OFF_H0B  (OFF_H0A + 64 * ROWS)      // 51200  (pong)
#define OFF_H1   (OFF_H0B + 64 * ROWS)      // 53248
#define OFF_B0   (OFF_H1 + 64 * ROWS)       // 55296
#define OFF_B1   (OFF_B0 + G4)
#define OFF_WI   (OFF_B1 + G4)
#define OFF_FCW  (OFF_WI + G4)
#define OFF_PP   (OFF_FCW + HH)             // 32 uc-groups x 32 rows
#define OFF_PV   (OFF_PP + 32 * ROWS)
#define OFF_FCB  (OFF_PV + ROWS)
#define SMEM_FLOATS (OFF_FCB + 4)
#define SMEM_BYTES  (SMEM_FLOATS * 4)       // ~228.8 KB

typedef unsigned long long ull;

// ---- packed f32x2 (Blackwell FFMA2 via PTX; ptxas won't auto-fuse) ----
__device__ __forceinline__ void fma2(ull &acc, ull a, ull b) {
    asm("fma.rn.f32x2 %0, %1, %2, %0;" : "+l"(acc) : "l"(a), "l"(b));
}
__device__ __forceinline__ ull pack2(float v) {
    ull r;
    asm("mov.b64 %0, {%1, %1};" : "=l"(r) : "r"(__float_as_uint(v)));
    return r;
}
__device__ __forceinline__ float2 unpack2(ull v) {
    unsigned int lo, hi;
    asm("mov.b64 {%0, %1}, %2;" : "=r"(lo), "=r"(hi) : "l"(v));
    return make_float2(__uint_as_float(lo), __uint_as_float(hi));
}

// ---- nonlinearities (MUFU ex2 + rcp, ~2 ulp) ----
__device__ __forceinline__ float sigm(float v) {
    return __fdividef(1.f, 1.f + __expf(-v));
}
__device__ __forceinline__ float tanh_(float v) {
    float a = fabsf(v);
    float e = __expf(-2.f * a);
    float r = __fdividef(1.f - e, 1.f + e);
    return copysignf(r, v);
}

// Thread tile: 4 batch rows (rq) x 8 gate-cols (uc -> 2 hidden units x 4 gates).
// acc[j][g]: ull = gate-col pair (g*64 + uc*2, +1) for batch row 4rq+j.

__device__ __forceinline__ void initacc(ull acc[4][4], const float* bias, int uc) {
    ull b[4];
    #pragma unroll
    for (int g = 0; g < 4; ++g)
        b[g] = *reinterpret_cast<const ull*>(bias + g * 64 + uc * 2);
    #pragma unroll
    for (int j = 0; j < 4; ++j)
        #pragma unroll
        for (int g = 0; g < 4; ++g)
            acc[j][g] = b[g];
}

// acc[j] += x[j] * Wih0-cols (rank-1 input term)
__device__ __forceinline__ void addx(ull acc[4][4], const float* w, int uc, const float xv[4]) {
    ull wg[4];
    #pragma unroll
    for (int g = 0; g < 4; ++g)
        wg[g] = *reinterpret_cast<const ull*>(w + g * 64 + uc * 2);
    #pragma unroll
    for (int j = 0; j < 4; ++j) {
        ull xx = pack2(xv[j]);
        #pragma unroll
        for (int g = 0; g < 4; ++g) fma2(acc[j][g], wg[g], xx);
    }
}

// gates += h @ Wt.  Wt: [64][PW] k-major (broadcast LDS.64 per gate);
// h: [64 units][32 rows], this thread owns rows 4rq..4rq+3 (one LDS.128 per k).
__device__ __forceinline__ void gemm64(ull acc[4][4], const float* __restrict__ wt,
                                       const float* __restrict__ hb, int rq, int uc) {
    const float* wbase = wt + uc * 2;
    const float4* h4 = reinterpret_cast<const float4*>(hb) + rq;   // stride 8 float4 per k
    #pragma unroll 8
    for (int k = 0; k < 64; ++k) {
        float4 hv = h4[k * 8];
        const float* p = wbase + k * PW;
        ull w0 = *reinterpret_cast<const ull*>(p);
        ull w1 = *reinterpret_cast<const ull*>(p + 64);
        ull w2 = *reinterpret_cast<const ull*>(p + 128);
        ull w3 = *reinterpret_cast<const ull*>(p + 192);
        ull h0 = pack2(hv.x), h1 = pack2(hv.y), h2 = pack2(hv.z), h3 = pack2(hv.w);
        fma2(acc[0][0], w0, h0); fma2(acc[1][0], w0, h1);
        fma2(acc[2][0], w0, h2); fma2(acc[3][0], w0, h3);
        fma2(acc[0][1], w1, h0); fma2(acc[1][1], w1, h1);
        fma2(acc[2][1], w1, h2); fma2(acc[3][1], w1, h3);
        fma2(acc[0][2], w2, h0); fma2(acc[1][2], w2, h1);
        fma2(acc[2][2], w2, h2); fma2(acc[3][2], w2, h3);
        fma2(acc[0][3], w3, h0); fma2(acc[1][3], w3, h1);
        fma2(acc[2][3], w3, h2); fma2(acc[3][3], w3, h3);
    }
}

// c/h: [row j][unit e] with units 2uc+e
__device__ __forceinline__ void cell(ull acc[4][4], float c[4][2], float h[4][2]) {
    #pragma unroll
    for (int j = 0; j < 4; ++j) {
        float2 iv = unpack2(acc[j][0]);
        float2 fv = unpack2(acc[j][1]);
        float2 gv = unpack2(acc[j][2]);
        float2 ov = unpack2(acc[j][3]);
        {
            float cn = sigm(fv.x) * c[j][0] + sigm(iv.x) * tanh_(gv.x);
            c[j][0] = cn;
            h[j][0] = sigm(ov.x) * tanh_(cn);
        }
        {
            float cn = sigm(fv.y) * c[j][1] + sigm(iv.y) * tanh_(gv.y);
            c[j][1] = cn;
            h[j][1] = sigm(ov.y) * tanh_(cn);
        }
    }
}

// H[(2uc+e)*32 + 4rq + j] = h[j][e]  -> two STS.128, conflict-free
__device__ __forceinline__ void storeh(float* H, int uc, int rq, const float h[4][2]) {
    *reinterpret_cast<float4*>(H + (2 * uc + 0) * ROWS + 4 * rq) =
        make_float4(h[0][0], h[1][0], h[2][0], h[3][0]);
    *reinterpret_cast<float4*>(H + (2 * uc + 1) * ROWS + 4 * rq) =
        make_float4(h[0][1], h[1][1], h[2][1], h[3][1]);
}

// Transpose-load weights into SMEM:  W*T[k][col] = W[col][k]
__device__ void load_weights(float* sm, const float* __restrict__ whh0,
                             const float* __restrict__ wih1, const float* __restrict__ whh1,
                             const float* __restrict__ b0, const float* __restrict__ b1,
                             const float* __restrict__ wih0) {
    float* W0T = sm + OFF_W0;
    float* W1T = sm + OFF_W1;
    int tid = threadIdx.x;
    for (int e = tid; e < G4 * HH; e += NTHREADS) {
        int col = e >> 6;
        int k = e & 63;
        W0T[k * PW + col] = whh0[e];
        W1T[k * PW + col] = wih1[e];
        W1T[(k + 64) * PW + col] = whh1[e];
    }
    sm[OFF_B0 + tid] = b0[tid];
    sm[OFF_B1 + tid] = b1[tid];
    sm[OFF_WI + tid] = wih0[tid];
}

__global__ void __launch_bounds__(NTHREADS, 1)
lstm_kernel(const float* __restrict__ x,
            const float* __restrict__ eWih0, const float* __restrict__ eWhh0,
            const float* __restrict__ eb0,
            const float* __restrict__ eWih1, const float* __restrict__ eWhh1,
            const float* __restrict__ eb1,
            const float* __restrict__ dWih0, const float* __restrict__ dWhh0,
            const float* __restrict__ db0,
            const float* __restrict__ dWih1, const float* __restrict__ dWhh1,
            const float* __restrict__ db1,
            const float* __restrict__ fcW, const float* __restrict__ fcb,
            float* __restrict__ out) {
    extern __shared__ float sm[];
    const int tid = threadIdx.x;
    const int rq = tid & 7;         // row-quad: batch rows 4rq..4rq+3
    const int uc = tid >> 3;        // 0..31: col-group (2 hidden units x 4 gates)
    const int row0 = blockIdx.x * ROWS + 4 * rq;

    float* H0buf[2] = { sm + OFF_H0A, sm + OFF_H0B };
    float* H1 = sm + OFF_H1;

    // ---------- encoder weights ----------
    load_weights(sm, eWhh0, eWih1, eWhh1, eb0, eb1, eWih0);
    for (int e = tid; e < 3 * 64 * ROWS; e += NTHREADS) sm[OFF_H0A + e] = 0.f;
    __syncthreads();

    float c0[4][2], c1[4][2];
    #pragma unroll
    for (int j = 0; j < 4; ++j) { c0[j][0] = c0[j][1] = 0.f; c1[j][0] = c1[j][1] = 0.f; }

    const float* xr = x + row0 * TT;
    float xv[4];
    #pragma unroll
    for (int j = 0; j < 4; ++j) xv[j] = xr[j * TT];

    // ---------- encoder: 365 sequential steps ----------
    for (int t = 0; t < TT; ++t) {
        float xn[4];
        #pragma unroll
        for (int j = 0; j < 4; ++j)
            xn[j] = (t + 1 < TT) ? xr[j * TT + t + 1] : 0.f;   // prefetch hides L2

        float* H0r = H0buf[t & 1];
        float* H0w = H0buf[(t + 1) & 1];

        ull acc[4][4];
        // layer 0: gates = b0 + x_t * Wih0 + h0 @ Whh0^T   (reads ping, writes pong)
        initacc(acc, sm + OFF_B0, uc);
        addx(acc, sm + OFF_WI, uc, xv);
        gemm64(acc, sm + OFF_W0, H0r, rq, uc);
        float h0[4][2];
        cell(acc, c0, h0);
        storeh(H0w, uc, rq, h0);
        __syncthreads();                       // h0 visible; (no WAR: ping-pong)

        // layer 1: gates = b1 + h0 @ Wih1^T + h1 @ Whh1^T
        initacc(acc, sm + OFF_B1, uc);
        gemm64(acc, sm + OFF_W1, H0w, rq, uc);
        gemm64(acc, sm + OFF_W1 + 64 * PW, H1, rq, uc);
        float h1[4][2];
        cell(acc, c1, h1);
        __syncthreads();                       // all reads of H1 done before overwrite
        storeh(H1, uc, rq, h1);

        #pragma unroll
        for (int j = 0; j < 4; ++j) xv[j] = xn[j];
    }
    __syncthreads();                           // final H1 stores visible; weight readers done

    // ---------- swap in decoder weights ----------
    load_weights(sm, dWhh0, dWih1, dWhh1, db0, db1, dWih0);
    if (tid < HH) sm[OFF_FCW + tid] = fcW[tid];
    if (tid == 0) sm[OFF_FCB] = fcb[0];
    __syncthreads();

    // ---------- decoder: 7 autoregressive steps ----------
    float din[4] = {0.f, 0.f, 0.f, 0.f};
    for (int s = 0; s < HORIZON; ++s) {
        int t = TT + s;
        float* H0r = H0buf[t & 1];
        float* H0w = H0buf[(t + 1) & 1];

        ull acc[4][4];
        initacc(acc, sm + OFF_B0, uc);
        addx(acc, sm + OFF_WI, uc, din);
        gemm64(acc, sm + OFF_W0, H0r, rq, uc);
        float h0[4][2];
        cell(acc, c0, h0);
        storeh(H0w, uc, rq, h0);
        __syncthreads();

        initacc(acc, sm + OFF_B1, uc);
        gemm64(acc, sm + OFF_W1, H0w, rq, uc);
        gemm64(acc, sm + OFF_W1 + 64 * PW, H1, rq, uc);
        float h1[4][2];
        cell(acc, c1, h1);

        // partial FC over this thread's 2 hidden units, per row
        float w0 = sm[OFF_FCW + 2 * uc], w1 = sm[OFF_FCW + 2 * uc + 1];
        float part[4];
        #pragma unroll
        for (int j = 0; j < 4; ++j) part[j] = h1[j][0] * w0 + h1[j][1] * w1;

        __syncthreads();                       // reads of old H1 done
        storeh(H1, uc, rq, h1);
        *reinterpret_cast<float4*>(sm + OFF_PP + uc * ROWS + 4 * rq) =
            make_float4(part[0], part[1], part[2], part[3]);
        __syncthreads();

        if (tid < ROWS) {
            float sum = sm[OFF_FCB];
            #pragma unroll
            for (int g = 0; g < 32; ++g) sum += sm[OFF_PP + g * ROWS + tid];
            out[(blockIdx.x * ROWS + tid) * HORIZON + s] = sum;
            sm[OFF_PV + tid] = sum;
        }
        __syncthreads();
        float4 dv = *reinterpret_cast<const float4*>(sm + OFF_PV + 4 * rq);
        din[0] = dv.x; din[1] = dv.y; din[2] = dv.z; din[3] = dv.w;
    }
}

extern "C" void kernel_launch(void* const* d_in, const int* in_sizes, int n_in,
                              void* d_out, int out_size) {
    cudaFuncSetAttribute(lstm_kernel, cudaFuncAttributeMaxDynamicSharedMemorySize, SMEM_BYTES);
    lstm_kernel<<<NCTA, NTHREADS, SMEM_BYTES>>>(
        (const float*)d_in[0],                                   // x
        (const float*)d_in[1], (const float*)d_in[2], (const float*)d_in[3],   // enc L0
        (const float*)d_in[4], (const float*)d_in[5], (const float*)d_in[6],   // enc L1
        (const float*)d_in[7], (const float*)d_in[8], (const float*)d_in[9],   // dec L0
        (const float*)d_in[10], (const float*)d_in[11], (const float*)d_in[12],// dec L1
        (const float*)d_in[13], (const float*)d_in[14],          // fc
        (float*)d_out);
}